// round 11
// baseline (speedup 1.0000x reference)
#include <cuda_runtime.h>
#include <cuda_bf16.h>

#define NN 1000000
#define NE 16000000
#define MAX_IT 100
#define TPB 128

// ---- device scratch (allocation-free rule: __device__ globals) ----
// Zero-initialized at module load. Post-loop cleanup restores the zero
// invariants (deg, nv, err) so every graph replay re-enters clean.
__device__ int   g_deg[NN];        // out-degree counts (0 at kernel entry)
__device__ float g_y[NN];          // v * alpha/deg (per-iteration gather src)
__device__ float g_nv[NN];         // SpMV accumulator (0 at kernel entry)
__device__ float g_err[MAX_IT + 1];// 0 at kernel entry
__device__ unsigned g_barcnt;      // grid barrier arrival count
__device__ unsigned g_sense;       // grid barrier generation

// Software grid barrier (all blocks co-resident by construction).
__device__ __forceinline__ void grid_bar(int nblocks) {
    __syncthreads();
    if (threadIdx.x == 0) {
        unsigned gen = *((volatile unsigned*)&g_sense);
        __threadfence();  // release
        unsigned a = atomicAdd(&g_barcnt, 1u);
        if (a == (unsigned)(nblocks - 1)) {
            g_barcnt = 0;
            __threadfence();
            atomicExch(&g_sense, gen + 1u);
        } else {
            while (*((volatile unsigned*)&g_sense) == gen) { __nanosleep(64); }
        }
        __threadfence();  // acquire (CCTL.IVALL: flush L1 before reads)
    }
    __syncthreads();
}

__device__ __forceinline__ float block_reduce_sum(float v) {
    __shared__ float sh[32];
    int lane = threadIdx.x & 31;
    int wid  = threadIdx.x >> 5;
    #pragma unroll
    for (int o = 16; o; o >>= 1) v += __shfl_down_sync(0xffffffffu, v, o);
    if (lane == 0) sh[wid] = v;
    __syncthreads();
    if (wid == 0) {
        v = (lane < (int)(blockDim.x >> 5)) ? sh[lane] : 0.0f;
        #pragma unroll
        for (int o = 16; o; o >>= 1) v += __shfl_down_sync(0xffffffffu, v, o);
    }
    return v;
}

__global__ void __launch_bounds__(TPB, 12)  // 128thr x 12 blk = 75% occ, finest tail
pagerank_persistent(const void* __restrict__ ei_raw, float* __restrict__ v,
                    int nblocks) {
    const int gsize = gridDim.x * blockDim.x;
    const int gtid  = blockIdx.x * blockDim.x + threadIdx.x;

    const float inv_n    = 1.0f / (float)NN;
    const float teleport = 0.15f * inv_n;
    const float thresh   = 1000000.0f * 1e-6f;  // N * TOL in float32

    // ---- dtype sniff: int64 vs int32 edge_index (certain after 8 checks) --
    bool is64 = true;
    {
        const long long* p = (const long long*)ei_raw;
        #pragma unroll
        for (int k = 0; k < 8; ++k) {
            long long x = p[k];
            if (x < 0 || x >= (long long)NN) is64 = false;
        }
    }
    const long long* rows64 = (const long long*)ei_raw;
    const long long* cols64 = rows64 + NE;
    const int*       rows32 = (const int*)ei_raw;
    const int*       cols32 = rows32 + NE;

    // ---- phase 0b: out-degree count (deg==0 at entry), 8-edge batches ----
    if (is64) {
        const int4* c4 = (const int4*)cols64;  // int4 = 2 int64 cols
        for (int e = gtid; e < NE / 8; e += gsize) {
            int4 a = __ldcs(&c4[4*e + 0]);
            int4 b = __ldcs(&c4[4*e + 1]);
            int4 c = __ldcs(&c4[4*e + 2]);
            int4 d = __ldcs(&c4[4*e + 3]);
            atomicAdd(&g_deg[a.x], 1); atomicAdd(&g_deg[a.z], 1);
            atomicAdd(&g_deg[b.x], 1); atomicAdd(&g_deg[b.z], 1);
            atomicAdd(&g_deg[c.x], 1); atomicAdd(&g_deg[c.z], 1);
            atomicAdd(&g_deg[d.x], 1); atomicAdd(&g_deg[d.z], 1);
        }
    } else {
        const int4* c4 = (const int4*)cols32;
        for (int e = gtid; e < NE / 8; e += gsize) {
            int4 a = __ldcs(&c4[2*e + 0]);
            int4 b = __ldcs(&c4[2*e + 1]);
            atomicAdd(&g_deg[a.x], 1); atomicAdd(&g_deg[a.y], 1);
            atomicAdd(&g_deg[a.z], 1); atomicAdd(&g_deg[a.w], 1);
            atomicAdd(&g_deg[b.x], 1); atomicAdd(&g_deg[b.y], 1);
            atomicAdd(&g_deg[b.z], 1); atomicAdd(&g_deg[b.w], 1);
        }
    }
    grid_bar(nblocks);

    // ---- phase 0c: iter-0 gather source  y = (alpha*inv_n)/deg ----
    // (teleport folded into C1; nv needs no init, it's 0 at entry)
    {
        const float a_over_n = 0.85f * inv_n;
        for (int i = gtid; i < NN; i += gsize)
            g_y[i] = a_over_n / (float)g_deg[i];  // inf if deg==0: never gathered
    }
    grid_bar(nblocks);

    // ---- power iterations ----
    for (int it = 0; it < MAX_IT; ++it) {
        // B: SpMV scatter nv[row] += y[col], 8-edge software pipeline:
        // all streams -> all gathers -> all fire-and-forget REDs.
        if (is64) {
            const int4* r4 = (const int4*)rows64;
            const int4* c4 = (const int4*)cols64;
            for (int e = gtid; e < NE / 8; e += gsize) {
                int4 ca = __ldcs(&c4[4*e+0]); int4 cb = __ldcs(&c4[4*e+1]);
                int4 cc = __ldcs(&c4[4*e+2]); int4 cd = __ldcs(&c4[4*e+3]);
                int4 ra = __ldcs(&r4[4*e+0]); int4 rb = __ldcs(&r4[4*e+1]);
                int4 rc = __ldcs(&r4[4*e+2]); int4 rd = __ldcs(&r4[4*e+3]);
                float y0 = __ldcg(&g_y[ca.x]), y1 = __ldcg(&g_y[ca.z]);
                float y2 = __ldcg(&g_y[cb.x]), y3 = __ldcg(&g_y[cb.z]);
                float y4 = __ldcg(&g_y[cc.x]), y5 = __ldcg(&g_y[cc.z]);
                float y6 = __ldcg(&g_y[cd.x]), y7 = __ldcg(&g_y[cd.z]);
                atomicAdd(&g_nv[ra.x], y0); atomicAdd(&g_nv[ra.z], y1);
                atomicAdd(&g_nv[rb.x], y2); atomicAdd(&g_nv[rb.z], y3);
                atomicAdd(&g_nv[rc.x], y4); atomicAdd(&g_nv[rc.z], y5);
                atomicAdd(&g_nv[rd.x], y6); atomicAdd(&g_nv[rd.z], y7);
            }
        } else {
            const int4* r4 = (const int4*)rows32;
            const int4* c4 = (const int4*)cols32;
            for (int e = gtid; e < NE / 8; e += gsize) {
                int4 ca = __ldcs(&c4[2*e+0]); int4 cb = __ldcs(&c4[2*e+1]);
                int4 ra = __ldcs(&r4[2*e+0]); int4 rb = __ldcs(&r4[2*e+1]);
                float y0 = __ldcg(&g_y[ca.x]), y1 = __ldcg(&g_y[ca.y]);
                float y2 = __ldcg(&g_y[ca.z]), y3 = __ldcg(&g_y[ca.w]);
                float y4 = __ldcg(&g_y[cb.x]), y5 = __ldcg(&g_y[cb.y]);
                float y6 = __ldcg(&g_y[cb.z]), y7 = __ldcg(&g_y[cb.w]);
                atomicAdd(&g_nv[ra.x], y0); atomicAdd(&g_nv[ra.y], y1);
                atomicAdd(&g_nv[ra.z], y2); atomicAdd(&g_nv[ra.w], y3);
                atomicAdd(&g_nv[rb.x], y4); atomicAdd(&g_nv[rb.y], y5);
                atomicAdd(&g_nv[rb.z], y6); atomicAdd(&g_nv[rb.w], y7);
            }
        }
        grid_bar(nblocks);

        // C1: err + commit v (+teleport fold) + inline nv re-zero.
        // Index i is thread-exclusive here; all REDs done (barrier above).
        float local = 0.0f;
        if (it == 0) {
            for (int i = gtid; i < NN; i += gsize) {
                float nv = g_nv[i] + teleport;
                local += fabsf(nv - inv_n);
                v[i] = nv;
                g_nv[i] = 0.0f;
            }
        } else {
            for (int i = gtid; i < NN; i += gsize) {
                float nv = g_nv[i] + teleport;
                local += fabsf(nv - v[i]);
                v[i] = nv;
                g_nv[i] = 0.0f;
            }
        }
        local = block_reduce_sum(local);
        if (threadIdx.x == 0) atomicAdd(&g_err[it], local);
        grid_bar(nblocks);

        float err = *((volatile float*)&g_err[it]);
        if (err < thresh) break;   // committed this iteration's new_v, like ref

        // C2: only if continuing — next gather source (nv already zeroed)
        for (int i = gtid; i < NN; i += gsize)
            g_y[i] = v[i] * (0.85f / (float)g_deg[i]);
        grid_bar(nblocks);
    }

    // ---- cleanup: restore zero invariants for the next graph replay ----
    // Reached only after the post-err barrier; a racing block that reads a
    // zeroed g_err still takes the same (break) decision. deg is not read
    // again after the final barrier. nv was re-zeroed inline in C1.
    {
        for (int i = gtid; i < NN; i += gsize) g_deg[i] = 0;
        for (int i = gtid; i <= MAX_IT; i += gsize) g_err[i] = 0.0f;
    }
}

extern "C" void kernel_launch(void* const* d_in, const int* in_sizes, int n_in,
                              void* d_out, int out_size) {
    (void)in_sizes; (void)n_in; (void)out_size;
    const void* ei = d_in[1];
    float* v = (float*)d_out;

    int dev = 0;
    cudaGetDevice(&dev);
    int sms = 0;
    cudaDeviceGetAttribute(&sms, cudaDevAttrMultiProcessorCount, dev);
    int maxb = 0;
    cudaOccupancyMaxActiveBlocksPerMultiprocessor(&maxb, pagerank_persistent, TPB, 0);
    if (maxb < 1) maxb = 1;
    int nblocks = sms * maxb;   // all co-resident -> grid barrier is safe

    pagerank_persistent<<<nblocks, TPB>>>(ei, v, nblocks);
}

// round 12
// speedup vs baseline: 1.0273x; 1.0273x over previous
#include <cuda_runtime.h>
#include <cuda_bf16.h>

#define NN 1000000
#define NE 16000000
#define MAX_IT 100
#define TPB 256

// ---- device scratch (allocation-free rule: __device__ globals) ----
// Zero-initialized at module load. Post-loop cleanup restores the zero
// invariants (deg, nv, err) so every graph replay re-enters clean.
__device__ int   g_deg[NN];        // out-degree counts (0 at kernel entry)
__device__ float g_y[NN];          // v * alpha/deg (per-iteration gather src)
__device__ float g_nv[NN];         // SpMV accumulator (0 at kernel entry)
__device__ float g_err[MAX_IT + 1];// 0 at kernel entry
__device__ unsigned g_barcnt;      // grid barrier arrival count
__device__ unsigned g_sense;       // grid barrier generation

// Software grid barrier (all blocks co-resident by construction).
__device__ __forceinline__ void grid_bar(int nblocks) {
    __syncthreads();
    if (threadIdx.x == 0) {
        unsigned gen = *((volatile unsigned*)&g_sense);
        __threadfence();  // release
        unsigned a = atomicAdd(&g_barcnt, 1u);
        if (a == (unsigned)(nblocks - 1)) {
            g_barcnt = 0;
            __threadfence();
            atomicExch(&g_sense, gen + 1u);
        } else {
            while (*((volatile unsigned*)&g_sense) == gen) { __nanosleep(64); }
        }
        __threadfence();  // acquire (CCTL.IVALL: flush L1 before reads)
    }
    __syncthreads();
}

__device__ __forceinline__ float block_reduce_sum(float v) {
    __shared__ float sh[32];
    int lane = threadIdx.x & 31;
    int wid  = threadIdx.x >> 5;
    #pragma unroll
    for (int o = 16; o; o >>= 1) v += __shfl_down_sync(0xffffffffu, v, o);
    if (lane == 0) sh[wid] = v;
    __syncthreads();
    if (wid == 0) {
        v = (lane < (int)(blockDim.x >> 5)) ? sh[lane] : 0.0f;
        #pragma unroll
        for (int o = 16; o; o >>= 1) v += __shfl_down_sync(0xffffffffu, v, o);
    }
    return v;
}

__global__ void __launch_bounds__(TPB, 6)   // champion shape: 256thr x 6/SM
pagerank_persistent(const void* __restrict__ ei_raw, float* __restrict__ v,
                    int nblocks) {
    const int gsize = gridDim.x * blockDim.x;
    const int gtid  = blockIdx.x * blockDim.x + threadIdx.x;

    const float inv_n    = 1.0f / (float)NN;
    const float teleport = 0.15f * inv_n;
    const float thresh   = 1000000.0f * 1e-6f;  // N * TOL in float32

    // ---- dtype sniff: int64 vs int32 edge_index (certain after 8 checks) --
    bool is64 = true;
    {
        const long long* p = (const long long*)ei_raw;
        #pragma unroll
        for (int k = 0; k < 8; ++k) {
            long long x = p[k];
            if (x < 0 || x >= (long long)NN) is64 = false;
        }
    }
    const long long* rows64 = (const long long*)ei_raw;
    const long long* cols64 = rows64 + NE;
    const int*       rows32 = (const int*)ei_raw;
    const int*       cols32 = rows32 + NE;

    // ---- phase 0b: out-degree count (deg==0 at entry), 8-edge batches ----
    if (is64) {
        const int4* c4 = (const int4*)cols64;  // int4 = 2 int64 cols
        for (int e = gtid; e < NE / 8; e += gsize) {
            int4 a = __ldcs(&c4[4*e + 0]);
            int4 b = __ldcs(&c4[4*e + 1]);
            int4 c = __ldcs(&c4[4*e + 2]);
            int4 d = __ldcs(&c4[4*e + 3]);
            atomicAdd(&g_deg[a.x], 1); atomicAdd(&g_deg[a.z], 1);
            atomicAdd(&g_deg[b.x], 1); atomicAdd(&g_deg[b.z], 1);
            atomicAdd(&g_deg[c.x], 1); atomicAdd(&g_deg[c.z], 1);
            atomicAdd(&g_deg[d.x], 1); atomicAdd(&g_deg[d.z], 1);
        }
    } else {
        const int4* c4 = (const int4*)cols32;
        for (int e = gtid; e < NE / 8; e += gsize) {
            int4 a = __ldcs(&c4[2*e + 0]);
            int4 b = __ldcs(&c4[2*e + 1]);
            atomicAdd(&g_deg[a.x], 1); atomicAdd(&g_deg[a.y], 1);
            atomicAdd(&g_deg[a.z], 1); atomicAdd(&g_deg[a.w], 1);
            atomicAdd(&g_deg[b.x], 1); atomicAdd(&g_deg[b.y], 1);
            atomicAdd(&g_deg[b.z], 1); atomicAdd(&g_deg[b.w], 1);
        }
    }
    grid_bar(nblocks);

    // ---- phase 0c: iter-0 gather source  y = (alpha*inv_n)/deg ----
    // (teleport folded into C1; nv needs no init, it's 0 at entry)
    {
        const float a_over_n = 0.85f * inv_n;
        for (int i = gtid; i < NN; i += gsize)
            g_y[i] = a_over_n / (float)g_deg[i];  // inf if deg==0: never gathered
    }
    grid_bar(nblocks);

    // ---- power iterations ----
    for (int it = 0; it < MAX_IT; ++it) {
        // B: SpMV scatter nv[row] += y[col], 8-edge software pipeline:
        // all streams -> all gathers -> all fire-and-forget REDs.
        if (is64) {
            const int4* r4 = (const int4*)rows64;
            const int4* c4 = (const int4*)cols64;
            for (int e = gtid; e < NE / 8; e += gsize) {
                int4 ca = __ldcs(&c4[4*e+0]); int4 cb = __ldcs(&c4[4*e+1]);
                int4 cc = __ldcs(&c4[4*e+2]); int4 cd = __ldcs(&c4[4*e+3]);
                int4 ra = __ldcs(&r4[4*e+0]); int4 rb = __ldcs(&r4[4*e+1]);
                int4 rc = __ldcs(&r4[4*e+2]); int4 rd = __ldcs(&r4[4*e+3]);
                float y0 = __ldcg(&g_y[ca.x]), y1 = __ldcg(&g_y[ca.z]);
                float y2 = __ldcg(&g_y[cb.x]), y3 = __ldcg(&g_y[cb.z]);
                float y4 = __ldcg(&g_y[cc.x]), y5 = __ldcg(&g_y[cc.z]);
                float y6 = __ldcg(&g_y[cd.x]), y7 = __ldcg(&g_y[cd.z]);
                atomicAdd(&g_nv[ra.x], y0); atomicAdd(&g_nv[ra.z], y1);
                atomicAdd(&g_nv[rb.x], y2); atomicAdd(&g_nv[rb.z], y3);
                atomicAdd(&g_nv[rc.x], y4); atomicAdd(&g_nv[rc.z], y5);
                atomicAdd(&g_nv[rd.x], y6); atomicAdd(&g_nv[rd.z], y7);
            }
        } else {
            const int4* r4 = (const int4*)rows32;
            const int4* c4 = (const int4*)cols32;
            for (int e = gtid; e < NE / 8; e += gsize) {
                int4 ca = __ldcs(&c4[2*e+0]); int4 cb = __ldcs(&c4[2*e+1]);
                int4 ra = __ldcs(&r4[2*e+0]); int4 rb = __ldcs(&r4[2*e+1]);
                float y0 = __ldcg(&g_y[ca.x]), y1 = __ldcg(&g_y[ca.y]);
                float y2 = __ldcg(&g_y[ca.z]), y3 = __ldcg(&g_y[ca.w]);
                float y4 = __ldcg(&g_y[cb.x]), y5 = __ldcg(&g_y[cb.y]);
                float y6 = __ldcg(&g_y[cb.z]), y7 = __ldcg(&g_y[cb.w]);
                atomicAdd(&g_nv[ra.x], y0); atomicAdd(&g_nv[ra.y], y1);
                atomicAdd(&g_nv[ra.z], y2); atomicAdd(&g_nv[ra.w], y3);
                atomicAdd(&g_nv[rb.x], y4); atomicAdd(&g_nv[rb.y], y5);
                atomicAdd(&g_nv[rb.z], y6); atomicAdd(&g_nv[rb.w], y7);
            }
        }
        grid_bar(nblocks);

        // C1: err + commit v (+teleport fold) + inline nv re-zero.
        // Index i is thread-exclusive here; all REDs done (barrier above).
        float local = 0.0f;
        if (it == 0) {
            for (int i = gtid; i < NN; i += gsize) {
                float nv = g_nv[i] + teleport;
                local += fabsf(nv - inv_n);
                v[i] = nv;
                g_nv[i] = 0.0f;
            }
        } else {
            for (int i = gtid; i < NN; i += gsize) {
                float nv = g_nv[i] + teleport;
                local += fabsf(nv - v[i]);
                v[i] = nv;
                g_nv[i] = 0.0f;
            }
        }
        local = block_reduce_sum(local);
        if (threadIdx.x == 0) atomicAdd(&g_err[it], local);
        grid_bar(nblocks);

        float err = *((volatile float*)&g_err[it]);
        if (err < thresh) break;   // committed this iteration's new_v, like ref

        // C2: only if continuing — next gather source (nv already zeroed)
        for (int i = gtid; i < NN; i += gsize)
            g_y[i] = v[i] * (0.85f / (float)g_deg[i]);
        grid_bar(nblocks);
    }

    // ---- cleanup: restore zero invariants for the next graph replay ----
    // Reached only after the post-err barrier; a racing block that reads a
    // zeroed g_err still takes the same (break) decision. deg is not read
    // again after the final barrier. nv was re-zeroed inline in C1.
    {
        int4* d4 = (int4*)g_deg;
        const int4 z4 = make_int4(0, 0, 0, 0);
        for (int i = gtid; i < NN / 4; i += gsize) d4[i] = z4;
        for (int i = gtid; i <= MAX_IT; i += gsize) g_err[i] = 0.0f;
    }
}

extern "C" void kernel_launch(void* const* d_in, const int* in_sizes, int n_in,
                              void* d_out, int out_size) {
    (void)in_sizes; (void)n_in; (void)out_size;
    const void* ei = d_in[1];
    float* v = (float*)d_out;

    int dev = 0;
    cudaGetDevice(&dev);
    int sms = 0;
    cudaDeviceGetAttribute(&sms, cudaDevAttrMultiProcessorCount, dev);
    int maxb = 0;
    cudaOccupancyMaxActiveBlocksPerMultiprocessor(&maxb, pagerank_persistent, TPB, 0);
    if (maxb < 1) maxb = 1;
    int nblocks = sms * maxb;   // all co-resident -> grid barrier is safe

    pagerank_persistent<<<nblocks, TPB>>>(ei, v, nblocks);
}

// round 13
// speedup vs baseline: 1.0290x; 1.0017x over previous
#include <cuda_runtime.h>
#include <cuda_bf16.h>

#define NN 1000000
#define NE 16000000
#define MAX_IT 100
#define TPB 256

// ---- device scratch (allocation-free rule: __device__ globals) ----
// Zero-initialized at module load. Post-loop cleanup restores the zero
// invariants (deg, nv, err) so every graph replay re-enters clean.
__device__ int   g_deg[NN];        // out-degree counts (0 at kernel entry)
__device__ float g_y[NN];          // v * alpha/deg (per-iteration gather src)
__device__ float g_nv[NN];         // SpMV accumulator (0 at kernel entry)
__device__ float g_err[MAX_IT + 1];// 0 at kernel entry
__device__ unsigned g_barcnt;      // grid barrier arrival count
__device__ unsigned g_sense;       // grid barrier generation

// Software grid barrier (all blocks co-resident by construction).
__device__ __forceinline__ void grid_bar(int nblocks) {
    __syncthreads();
    if (threadIdx.x == 0) {
        unsigned gen = *((volatile unsigned*)&g_sense);
        __threadfence();  // release
        unsigned a = atomicAdd(&g_barcnt, 1u);
        if (a == (unsigned)(nblocks - 1)) {
            g_barcnt = 0;
            __threadfence();
            atomicExch(&g_sense, gen + 1u);
        } else {
            while (*((volatile unsigned*)&g_sense) == gen) { __nanosleep(64); }
        }
        __threadfence();  // acquire (CCTL.IVALL: flush L1 before reads)
    }
    __syncthreads();
}

__device__ __forceinline__ float block_reduce_sum(float v) {
    __shared__ float sh[32];
    int lane = threadIdx.x & 31;
    int wid  = threadIdx.x >> 5;
    #pragma unroll
    for (int o = 16; o; o >>= 1) v += __shfl_down_sync(0xffffffffu, v, o);
    if (lane == 0) sh[wid] = v;
    __syncthreads();
    if (wid == 0) {
        v = (lane < (int)(blockDim.x >> 5)) ? sh[lane] : 0.0f;
        #pragma unroll
        for (int o = 16; o; o >>= 1) v += __shfl_down_sync(0xffffffffu, v, o);
    }
    return v;
}

__global__ void __launch_bounds__(TPB, 6)   // champion shape: 256thr x 6/SM
pagerank_persistent(const void* __restrict__ ei_raw, float* __restrict__ v,
                    int nblocks) {
    const int gsize = gridDim.x * blockDim.x;
    const int gtid  = blockIdx.x * blockDim.x + threadIdx.x;

    const float inv_n    = 1.0f / (float)NN;
    const float teleport = 0.15f * inv_n;
    const float thresh   = 1000000.0f * 1e-6f;  // N * TOL in float32

    // ---- dtype sniff: int64 vs int32 edge_index (certain after 8 checks) --
    bool is64 = true;
    {
        const long long* p = (const long long*)ei_raw;
        #pragma unroll
        for (int k = 0; k < 8; ++k) {
            long long x = p[k];
            if (x < 0 || x >= (long long)NN) is64 = false;
        }
    }
    const long long* rows64 = (const long long*)ei_raw;
    const long long* cols64 = rows64 + NE;
    const int*       rows32 = (const int*)ei_raw;
    const int*       cols32 = rows32 + NE;

    // ---- phase 0b: out-degree count (deg==0 at entry), 8-edge batches ----
    if (is64) {
        const int4* c4 = (const int4*)cols64;  // int4 = 2 int64 cols
        for (int e = gtid; e < NE / 8; e += gsize) {
            int4 a = __ldcs(&c4[4*e + 0]);
            int4 b = __ldcs(&c4[4*e + 1]);
            int4 c = __ldcs(&c4[4*e + 2]);
            int4 d = __ldcs(&c4[4*e + 3]);
            atomicAdd(&g_deg[a.x], 1); atomicAdd(&g_deg[a.z], 1);
            atomicAdd(&g_deg[b.x], 1); atomicAdd(&g_deg[b.z], 1);
            atomicAdd(&g_deg[c.x], 1); atomicAdd(&g_deg[c.z], 1);
            atomicAdd(&g_deg[d.x], 1); atomicAdd(&g_deg[d.z], 1);
        }
    } else {
        const int4* c4 = (const int4*)cols32;
        for (int e = gtid; e < NE / 8; e += gsize) {
            int4 a = __ldcs(&c4[2*e + 0]);
            int4 b = __ldcs(&c4[2*e + 1]);
            atomicAdd(&g_deg[a.x], 1); atomicAdd(&g_deg[a.y], 1);
            atomicAdd(&g_deg[a.z], 1); atomicAdd(&g_deg[a.w], 1);
            atomicAdd(&g_deg[b.x], 1); atomicAdd(&g_deg[b.y], 1);
            atomicAdd(&g_deg[b.z], 1); atomicAdd(&g_deg[b.w], 1);
        }
    }
    grid_bar(nblocks);

    // ---- phase 0c: iter-0 gather source  y = (alpha*inv_n)/deg ----
    // (teleport folded into C1; nv needs no init, it's 0 at entry)
    {
        const float a_over_n = 0.85f * inv_n;
        for (int i = gtid; i < NN; i += gsize)
            g_y[i] = a_over_n / (float)g_deg[i];  // inf if deg==0: never gathered
    }
    grid_bar(nblocks);

    // ---- power iterations ----
    for (int it = 0; it < MAX_IT; ++it) {
        // B: SpMV scatter nv[row] += y[col], 8-edge software pipeline:
        // all streams -> all gathers -> all fire-and-forget REDs.
        if (is64) {
            const int4* r4 = (const int4*)rows64;
            const int4* c4 = (const int4*)cols64;
            for (int e = gtid; e < NE / 8; e += gsize) {
                int4 ca = __ldcs(&c4[4*e+0]); int4 cb = __ldcs(&c4[4*e+1]);
                int4 cc = __ldcs(&c4[4*e+2]); int4 cd = __ldcs(&c4[4*e+3]);
                int4 ra = __ldcs(&r4[4*e+0]); int4 rb = __ldcs(&r4[4*e+1]);
                int4 rc = __ldcs(&r4[4*e+2]); int4 rd = __ldcs(&r4[4*e+3]);
                float y0 = __ldcg(&g_y[ca.x]), y1 = __ldcg(&g_y[ca.z]);
                float y2 = __ldcg(&g_y[cb.x]), y3 = __ldcg(&g_y[cb.z]);
                float y4 = __ldcg(&g_y[cc.x]), y5 = __ldcg(&g_y[cc.z]);
                float y6 = __ldcg(&g_y[cd.x]), y7 = __ldcg(&g_y[cd.z]);
                atomicAdd(&g_nv[ra.x], y0); atomicAdd(&g_nv[ra.z], y1);
                atomicAdd(&g_nv[rb.x], y2); atomicAdd(&g_nv[rb.z], y3);
                atomicAdd(&g_nv[rc.x], y4); atomicAdd(&g_nv[rc.z], y5);
                atomicAdd(&g_nv[rd.x], y6); atomicAdd(&g_nv[rd.z], y7);
            }
        } else {
            const int4* r4 = (const int4*)rows32;
            const int4* c4 = (const int4*)cols32;
            for (int e = gtid; e < NE / 8; e += gsize) {
                int4 ca = __ldcs(&c4[2*e+0]); int4 cb = __ldcs(&c4[2*e+1]);
                int4 ra = __ldcs(&r4[2*e+0]); int4 rb = __ldcs(&r4[2*e+1]);
                float y0 = __ldcg(&g_y[ca.x]), y1 = __ldcg(&g_y[ca.y]);
                float y2 = __ldcg(&g_y[ca.z]), y3 = __ldcg(&g_y[ca.w]);
                float y4 = __ldcg(&g_y[cb.x]), y5 = __ldcg(&g_y[cb.y]);
                float y6 = __ldcg(&g_y[cb.z]), y7 = __ldcg(&g_y[cb.w]);
                atomicAdd(&g_nv[ra.x], y0); atomicAdd(&g_nv[ra.y], y1);
                atomicAdd(&g_nv[ra.z], y2); atomicAdd(&g_nv[ra.w], y3);
                atomicAdd(&g_nv[rb.x], y4); atomicAdd(&g_nv[rb.y], y5);
                atomicAdd(&g_nv[rb.z], y6); atomicAdd(&g_nv[rb.w], y7);
            }
        }
        grid_bar(nblocks);

        // C1: err + commit v (+teleport fold) + inline nv re-zero.
        // Index i is thread-exclusive here; all REDs done (barrier above).
        float local = 0.0f;
        if (it == 0) {
            for (int i = gtid; i < NN; i += gsize) {
                float nv = g_nv[i] + teleport;
                local += fabsf(nv - inv_n);
                v[i] = nv;
                g_nv[i] = 0.0f;
            }
        } else {
            for (int i = gtid; i < NN; i += gsize) {
                float nv = g_nv[i] + teleport;
                local += fabsf(nv - v[i]);
                v[i] = nv;
                g_nv[i] = 0.0f;
            }
        }
        local = block_reduce_sum(local);
        if (threadIdx.x == 0) atomicAdd(&g_err[it], local);
        grid_bar(nblocks);

        float err = *((volatile float*)&g_err[it]);
        if (err < thresh) break;   // committed this iteration's new_v, like ref

        // C2: only if continuing — next gather source (nv already zeroed)
        for (int i = gtid; i < NN; i += gsize)
            g_y[i] = v[i] * (0.85f / (float)g_deg[i]);
        grid_bar(nblocks);
    }

    // ---- cleanup: restore zero invariants for the next graph replay ----
    // Reached only after the post-err barrier; a racing block that reads a
    // zeroed g_err still takes the same (break) decision. deg is not read
    // again after the final barrier. nv was re-zeroed inline in C1.
    {
        for (int i = gtid; i < NN; i += gsize) g_deg[i] = 0;
        for (int i = gtid; i <= MAX_IT; i += gsize) g_err[i] = 0.0f;
    }
}

extern "C" void kernel_launch(void* const* d_in, const int* in_sizes, int n_in,
                              void* d_out, int out_size) {
    (void)in_sizes; (void)n_in; (void)out_size;
    const void* ei = d_in[1];
    float* v = (float*)d_out;

    int dev = 0;
    cudaGetDevice(&dev);
    int sms = 0;
    cudaDeviceGetAttribute(&sms, cudaDevAttrMultiProcessorCount, dev);
    int maxb = 0;
    cudaOccupancyMaxActiveBlocksPerMultiprocessor(&maxb, pagerank_persistent, TPB, 0);
    if (maxb < 1) maxb = 1;
    int nblocks = sms * maxb;   // all co-resident -> grid barrier is safe

    pagerank_persistent<<<nblocks, TPB>>>(ei, v, nblocks);
}

// round 14
// speedup vs baseline: 1.0508x; 1.0212x over previous
#include <cuda_runtime.h>
#include <cuda_bf16.h>

#define NN 1000000
#define NE 16000000
#define MAX_IT 100
#define TPB 256

// ---- device scratch (allocation-free rule: __device__ globals) ----
// Zero-initialized at module load. Post-loop cleanup restores the zero
// invariants (deg, nv, err) so every graph replay re-enters clean.
__device__ int   g_deg[NN];        // out-degree counts (0 at kernel entry)
__device__ float g_y[NN];          // v * alpha/deg (per-iteration gather src)
__device__ float g_nv[NN];         // SpMV accumulator (0 at kernel entry)
__device__ float g_err[MAX_IT + 1];// 0 at kernel entry
__device__ unsigned g_barcnt;      // grid barrier arrival count
__device__ unsigned g_sense;       // grid barrier generation

// Software grid barrier (all blocks co-resident by construction).
__device__ __forceinline__ void grid_bar(int nblocks) {
    __syncthreads();
    if (threadIdx.x == 0) {
        unsigned gen = *((volatile unsigned*)&g_sense);
        __threadfence();  // release
        unsigned a = atomicAdd(&g_barcnt, 1u);
        if (a == (unsigned)(nblocks - 1)) {
            g_barcnt = 0;
            __threadfence();
            atomicExch(&g_sense, gen + 1u);
        } else {
            while (*((volatile unsigned*)&g_sense) == gen) { __nanosleep(64); }
        }
        __threadfence();  // acquire (CCTL.IVALL: flush L1 before reads)
    }
    __syncthreads();
}

__device__ __forceinline__ float block_reduce_sum(float v) {
    __shared__ float sh[32];
    int lane = threadIdx.x & 31;
    int wid  = threadIdx.x >> 5;
    #pragma unroll
    for (int o = 16; o; o >>= 1) v += __shfl_down_sync(0xffffffffu, v, o);
    if (lane == 0) sh[wid] = v;
    __syncthreads();
    if (wid == 0) {
        v = (lane < (int)(blockDim.x >> 5)) ? sh[lane] : 0.0f;
        #pragma unroll
        for (int o = 16; o; o >>= 1) v += __shfl_down_sync(0xffffffffu, v, o);
    }
    return v;
}

__global__ void __launch_bounds__(TPB, 6)   // champion shape: 256thr x 6/SM
pagerank_persistent(const void* __restrict__ ei_raw, float* __restrict__ v,
                    int nblocks) {
    const int gsize = gridDim.x * blockDim.x;
    const int gtid  = blockIdx.x * blockDim.x + threadIdx.x;

    const float inv_n    = 1.0f / (float)NN;
    const float teleport = 0.15f * inv_n;
    const float thresh   = 1000000.0f * 1e-6f;  // N * TOL in float32

    // ---- dtype sniff: int64 vs int32 edge_index (certain after 8 checks) --
    bool is64 = true;
    {
        const long long* p = (const long long*)ei_raw;
        #pragma unroll
        for (int k = 0; k < 8; ++k) {
            long long x = p[k];
            if (x < 0 || x >= (long long)NN) is64 = false;
        }
    }
    const long long* rows64 = (const long long*)ei_raw;
    const long long* cols64 = rows64 + NE;
    const int*       rows32 = (const int*)ei_raw;
    const int*       cols32 = rows32 + NE;

    // ---- phase 0b: out-degree count (deg==0 at entry), 8-edge batches ----
    if (is64) {
        const int4* c4 = (const int4*)cols64;  // int4 = 2 int64 cols
        for (int e = gtid; e < NE / 8; e += gsize) {
            int4 a = __ldcs(&c4[4*e + 0]);
            int4 b = __ldcs(&c4[4*e + 1]);
            int4 c = __ldcs(&c4[4*e + 2]);
            int4 d = __ldcs(&c4[4*e + 3]);
            atomicAdd(&g_deg[a.x], 1); atomicAdd(&g_deg[a.z], 1);
            atomicAdd(&g_deg[b.x], 1); atomicAdd(&g_deg[b.z], 1);
            atomicAdd(&g_deg[c.x], 1); atomicAdd(&g_deg[c.z], 1);
            atomicAdd(&g_deg[d.x], 1); atomicAdd(&g_deg[d.z], 1);
        }
    } else {
        const int4* c4 = (const int4*)cols32;
        for (int e = gtid; e < NE / 8; e += gsize) {
            int4 a = __ldcs(&c4[2*e + 0]);
            int4 b = __ldcs(&c4[2*e + 1]);
            atomicAdd(&g_deg[a.x], 1); atomicAdd(&g_deg[a.y], 1);
            atomicAdd(&g_deg[a.z], 1); atomicAdd(&g_deg[a.w], 1);
            atomicAdd(&g_deg[b.x], 1); atomicAdd(&g_deg[b.y], 1);
            atomicAdd(&g_deg[b.z], 1); atomicAdd(&g_deg[b.w], 1);
        }
    }
    grid_bar(nblocks);

    // ---- phase 0c: iter-0 gather source  y = (alpha*inv_n)/deg ----
    // (teleport folded into C1; nv needs no init, it's 0 at entry)
    {
        const float a_over_n = 0.85f * inv_n;
        for (int i = gtid; i < NN; i += gsize)
            g_y[i] = a_over_n / (float)g_deg[i];  // inf if deg==0: never gathered
    }
    grid_bar(nblocks);

    // ---- power iterations ----
    for (int it = 0; it < MAX_IT; ++it) {
        // B: SpMV scatter nv[row] += y[col], 8-edge software pipeline:
        // all streams -> all gathers -> all fire-and-forget REDs.
        if (is64) {
            const int4* r4 = (const int4*)rows64;
            const int4* c4 = (const int4*)cols64;
            for (int e = gtid; e < NE / 8; e += gsize) {
                int4 ca = __ldcs(&c4[4*e+0]); int4 cb = __ldcs(&c4[4*e+1]);
                int4 cc = __ldcs(&c4[4*e+2]); int4 cd = __ldcs(&c4[4*e+3]);
                int4 ra = __ldcs(&r4[4*e+0]); int4 rb = __ldcs(&r4[4*e+1]);
                int4 rc = __ldcs(&r4[4*e+2]); int4 rd = __ldcs(&r4[4*e+3]);
                float y0 = __ldcg(&g_y[ca.x]), y1 = __ldcg(&g_y[ca.z]);
                float y2 = __ldcg(&g_y[cb.x]), y3 = __ldcg(&g_y[cb.z]);
                float y4 = __ldcg(&g_y[cc.x]), y5 = __ldcg(&g_y[cc.z]);
                float y6 = __ldcg(&g_y[cd.x]), y7 = __ldcg(&g_y[cd.z]);
                atomicAdd(&g_nv[ra.x], y0); atomicAdd(&g_nv[ra.z], y1);
                atomicAdd(&g_nv[rb.x], y2); atomicAdd(&g_nv[rb.z], y3);
                atomicAdd(&g_nv[rc.x], y4); atomicAdd(&g_nv[rc.z], y5);
                atomicAdd(&g_nv[rd.x], y6); atomicAdd(&g_nv[rd.z], y7);
            }
        } else {
            const int4* r4 = (const int4*)rows32;
            const int4* c4 = (const int4*)cols32;
            for (int e = gtid; e < NE / 8; e += gsize) {
                int4 ca = __ldcs(&c4[2*e+0]); int4 cb = __ldcs(&c4[2*e+1]);
                int4 ra = __ldcs(&r4[2*e+0]); int4 rb = __ldcs(&r4[2*e+1]);
                float y0 = __ldcg(&g_y[ca.x]), y1 = __ldcg(&g_y[ca.y]);
                float y2 = __ldcg(&g_y[ca.z]), y3 = __ldcg(&g_y[ca.w]);
                float y4 = __ldcg(&g_y[cb.x]), y5 = __ldcg(&g_y[cb.y]);
                float y6 = __ldcg(&g_y[cb.z]), y7 = __ldcg(&g_y[cb.w]);
                atomicAdd(&g_nv[ra.x], y0); atomicAdd(&g_nv[ra.y], y1);
                atomicAdd(&g_nv[ra.z], y2); atomicAdd(&g_nv[ra.w], y3);
                atomicAdd(&g_nv[rb.x], y4); atomicAdd(&g_nv[rb.y], y5);
                atomicAdd(&g_nv[rb.z], y6); atomicAdd(&g_nv[rb.w], y7);
            }
        }
        grid_bar(nblocks);

        // C1: err + commit v (+teleport fold) + inline nv re-zero.
        // Index i is thread-exclusive here; all REDs done (barrier above).
        float local = 0.0f;
        if (it == 0) {
            for (int i = gtid; i < NN; i += gsize) {
                float nv = g_nv[i] + teleport;
                local += fabsf(nv - inv_n);
                v[i] = nv;
                g_nv[i] = 0.0f;
            }
        } else {
            for (int i = gtid; i < NN; i += gsize) {
                float nv = g_nv[i] + teleport;
                local += fabsf(nv - v[i]);
                v[i] = nv;
                g_nv[i] = 0.0f;
            }
        }
        local = block_reduce_sum(local);
        if (threadIdx.x == 0) atomicAdd(&g_err[it], local);
        grid_bar(nblocks);

        float err = *((volatile float*)&g_err[it]);
        if (err < thresh) break;   // committed this iteration's new_v, like ref

        // C2: only if continuing — next gather source (nv already zeroed)
        for (int i = gtid; i < NN; i += gsize)
            g_y[i] = v[i] * (0.85f / (float)g_deg[i]);
        grid_bar(nblocks);
    }

    // ---- cleanup: restore zero invariants for the next graph replay ----
    // Reached only after the post-err barrier; a racing block that reads a
    // zeroed g_err still takes the same (break) decision. deg is not read
    // again after the final barrier. nv was re-zeroed inline in C1.
    {
        for (int i = gtid; i < NN; i += gsize) g_deg[i] = 0;
        for (int i = gtid; i <= MAX_IT; i += gsize) g_err[i] = 0.0f;
    }
}

extern "C" void kernel_launch(void* const* d_in, const int* in_sizes, int n_in,
                              void* d_out, int out_size) {
    (void)in_sizes; (void)n_in; (void)out_size;
    const void* ei = d_in[1];
    float* v = (float*)d_out;

    int dev = 0;
    cudaGetDevice(&dev);
    int sms = 0;
    cudaDeviceGetAttribute(&sms, cudaDevAttrMultiProcessorCount, dev);
    int maxb = 0;
    cudaOccupancyMaxActiveBlocksPerMultiprocessor(&maxb, pagerank_persistent, TPB, 0);
    if (maxb < 1) maxb = 1;
    int nblocks = sms * maxb;   // all co-resident -> grid barrier is safe

    pagerank_persistent<<<nblocks, TPB>>>(ei, v, nblocks);
}